// round 17
// baseline (speedup 1.0000x reference)
#include <cuda_runtime.h>
#include <cuda_fp16.h>
#include <stdint.h>
#include <stddef.h>

#define B_ 4
#define S_ 2048
#define HID_ 768
#define H_ 12
#define D_ 64
#define BH_ 48
#define MROWS 8192
#define OUTE 6291456
#define WE 589824
#define SCALE_ 0.125f
#define C2_ 0.18033688f   // 0.125 * log2(e)

__device__ float g_scratch[36962304ull];
__device__ uint32_t g_bm[524288];
__device__ float g_rsum[BH_ * S_];
// e-scratch: [bh 48][qt 16][kt 32][4096 words] of half2
__device__ uint32_t g_escr[100663296ull];

// ---------------------------------------------------------------------------
__device__ __forceinline__ uint32_t ph2(float a, float b) {
    __half2 h = __floats2half2_rn(a, b);
    return *(uint32_t*)&h;
}

__device__ __forceinline__ void mma16(float* c,
    uint32_t a0, uint32_t a1, uint32_t a2, uint32_t a3,
    uint32_t b0, uint32_t b1)
{
    asm volatile(
        "mma.sync.aligned.m16n8k16.row.col.f32.f16.f16.f32 "
        "{%0,%1,%2,%3}, {%4,%5,%6,%7}, {%8,%9}, {%0,%1,%2,%3};"
        : "+f"(c[0]), "+f"(c[1]), "+f"(c[2]), "+f"(c[3])
        : "r"(a0), "r"(a1), "r"(a2), "r"(a3), "r"(b0), "r"(b1));
}
__device__ __forceinline__ void ldsm4(uint32_t& r0, uint32_t& r1,
                                      uint32_t& r2, uint32_t& r3, uint32_t saddr)
{
    asm volatile("ldmatrix.sync.aligned.m8n8.x4.shared.b16 {%0,%1,%2,%3}, [%4];"
        : "=r"(r0), "=r"(r1), "=r"(r2), "=r"(r3) : "r"(saddr));
}
__device__ __forceinline__ void ldsm4t(uint32_t& r0, uint32_t& r1,
                                       uint32_t& r2, uint32_t& r3, uint32_t saddr)
{
    asm volatile("ldmatrix.sync.aligned.m8n8.x4.trans.shared.b16 {%0,%1,%2,%3}, [%4];"
        : "=r"(r0), "=r"(r1), "=r"(r2), "=r"(r3) : "r"(saddr));
}
__device__ __forceinline__ void cpa16(uint32_t saddr, const void* g) {
    asm volatile("cp.async.cg.shared.global [%0], [%1], 16;"
        :: "r"(saddr), "l"(g));
}
#define CP_COMMIT() asm volatile("cp.async.commit_group;" ::: "memory")
#define CP_WAIT0()  asm volatile("cp.async.wait_group 0;" ::: "memory")

// ---------------------------------------------------------------------------
// prep_all: bitmask + all 7 fp32->fp16 conversions in one launch.
// ---------------------------------------------------------------------------
__global__ __launch_bounds__(256) void prep_all(
    const float* __restrict__ Q, const float* __restrict__ K, const float* __restrict__ V,
    const float* __restrict__ Wq, const float* __restrict__ Wk,
    const float* __restrict__ Wv, const float* __restrict__ Wo,
    __half* __restrict__ rXq, __half* __restrict__ rXk, __half* __restrict__ rXv,
    __half* __restrict__ rWq, __half* __restrict__ rWk,
    __half* __restrict__ rWv, __half* __restrict__ rWo,
    const int* __restrict__ mask, uint32_t* __restrict__ bm)
{
    int bid = blockIdx.x;
    if (bid < 18432) {
        int which = bid / 6144;
        int lb = bid - which * 6144;
        const float* src = (which == 0) ? Q : (which == 1) ? K : V;
        __half* dst = (which == 0) ? rXq : (which == 1) ? rXk : rXv;
        size_t i = (size_t)lb * 256 + threadIdx.x;
        float4 v = ((const float4*)src)[i];
        ((uint2*)dst)[i] = make_uint2(ph2(v.x, v.y), ph2(v.z, v.w));
    } else if (bid < 20736) {
        int r = bid - 18432;
        int which = r / 576;
        int lb = r - which * 576;
        const float* src = (which == 0) ? Wq : (which == 1) ? Wk
                         : (which == 2) ? Wv : Wo;
        __half* dst = (which == 0) ? rWq : (which == 1) ? rWk
                    : (which == 2) ? rWv : rWo;
        size_t i = (size_t)lb * 256 + threadIdx.x;
        float4 v = ((const float4*)src)[i];
        ((uint2*)dst)[i] = make_uint2(ph2(v.x, v.y), ph2(v.z, v.w));
    } else {
        int idx = (bid - 20736) * 256 + threadIdx.x;
        const int* p = mask + (size_t)idx * 32;
        uint32_t r = 0;
#pragma unroll
        for (int j = 0; j < 8; j++) {
            int4 v = *(const int4*)(p + 4 * j);
            r |= (v.x != 0 ? 1u : 0u) << (4 * j);
            r |= (v.y != 0 ? 1u : 0u) << (4 * j + 1);
            r |= (v.z != 0 ? 1u : 0u) << (4 * j + 2);
            r |= (v.w != 0 ? 1u : 0u) << (4 * j + 3);
        }
        bm[idx] = r;
    }
}

// ---------------------------------------------------------------------------
// fp16 projection GEMM, 128x128, BK=64 (R16 proven) — used for QKV.
// ---------------------------------------------------------------------------
#define XP 36
#define WP 68
#define XBUFW (128 * XP)
#define WBUFW (64 * WP)
#define GW_OFF (2 * XBUFW)
#define GEMM_SMEM ((2 * XBUFW + 2 * WBUFW) * 4)

__global__ __launch_bounds__(256, 2) void gemm_qkv(
    const __half* __restrict__ Xq, const __half* __restrict__ Xk, const __half* __restrict__ Xv,
    const __half* __restrict__ Wq, const __half* __restrict__ Wk, const __half* __restrict__ Wv,
    const float* __restrict__ bq, const float* __restrict__ bk, const float* __restrict__ bv,
    __half* __restrict__ oq, __half* __restrict__ ok, __half* __restrict__ ov)
{
    extern __shared__ uint32_t sh[];
    const int z = blockIdx.z;
    const __half* X   = (z == 0) ? Xq : (z == 1) ? Xk : Xv;
    const __half* W   = (z == 0) ? Wq : (z == 1) ? Wk : Wv;
    const float* bias = (z == 0) ? bq : (z == 1) ? bk : bv;
    __half* out       = (z == 0) ? oq : (z == 1) ? ok : ov;
    const int m0 = blockIdx.y * 128, n0 = blockIdx.x * 128;

    uint32_t sbase;
    asm("{ .reg .u64 t0; cvta.to.shared.u64 t0, %1; cvt.u32.u64 %0, t0; }"
        : "=r"(sbase) : "l"(sh));

    const int tid  = threadIdx.x;
    const int w    = tid >> 5;
    const int lane = tid & 31;
    const int g    = lane >> 2;
    const int t    = lane & 3;
    const int wm   = (w & 1) * 64;
    const int wn   = (w >> 1) * 32;

    float acc[4][4][4];
#pragma unroll
    for (int mi = 0; mi < 4; mi++)
#pragma unroll
        for (int ni = 0; ni < 4; ni++)
#pragma unroll
            for (int r = 0; r < 4; r++) acc[mi][ni][r] = 0.f;

    const uint32_t xbase = sbase +
        (uint32_t)((wm + (lane & 15)) * XP + (lane >> 4) * 4) * 4;
    const uint32_t wbase = sbase +
        (uint32_t)(GW_OFF + (lane & 15) * WP + wn / 2 + (lane >> 4) * 4) * 4;

    auto stage = [&](int k0, int buf) {
#pragma unroll
        for (int i = 0; i < 4; i++) {
            int u = tid + 256 * i;
            int r = u >> 3, c = u & 7;
            cpa16(sbase + (uint32_t)(buf * XBUFW + r * XP + c * 4) * 4,
                  X + (size_t)(m0 + r) * HID_ + k0 + c * 8);
        }
#pragma unroll
        for (int i = 0; i < 4; i++) {
            int u = tid + 256 * i;
            int r = u >> 4, c = u & 15;
            cpa16(sbase + (uint32_t)(GW_OFF + buf * WBUFW + r * WP + c * 4) * 4,
                  W + (size_t)(k0 + r) * HID_ + n0 + c * 8);
        }
    };

    stage(0, 0);
    CP_COMMIT(); CP_WAIT0();
    __syncthreads();

    int buf = 0;
    for (int kt = 0; kt < 12; kt++) {
        if (kt < 11) { stage((kt + 1) * 64, buf ^ 1); CP_COMMIT(); }

#pragma unroll
        for (int s = 0; s < 4; s++) {
            uint32_t a[4][4];
#pragma unroll
            for (int mi = 0; mi < 4; mi++)
                ldsm4(a[mi][0], a[mi][1], a[mi][2], a[mi][3],
                      xbase + (uint32_t)(buf * XBUFW + mi * 16 * XP + s * 8) * 4);
#pragma unroll
            for (int j = 0; j < 2; j++) {
                uint32_t b0, b1, b2, b3;
                ldsm4t(b0, b1, b2, b3,
                       wbase + (uint32_t)(buf * WBUFW + s * 16 * WP + 8 * j) * 4);
#pragma unroll
                for (int mi = 0; mi < 4; mi++) {
                    mma16(acc[mi][2 * j],     a[mi][0], a[mi][1], a[mi][2], a[mi][3], b0, b1);
                    mma16(acc[mi][2 * j + 1], a[mi][0], a[mi][1], a[mi][2], a[mi][3], b2, b3);
                }
            }
        }

        if (kt < 11) CP_WAIT0();
        __syncthreads();
        buf ^= 1;
    }

#pragma unroll
    for (int mi = 0; mi < 4; mi++) {
        int r0 = m0 + wm + 16 * mi + g;
        int r1 = r0 + 8;
#pragma unroll
        for (int ni = 0; ni < 4; ni++) {
            int col = n0 + wn + 8 * ni + 2 * t;
            float bb0 = bias[col], bb1 = bias[col + 1];
            float c00 = acc[mi][ni][0] + bb0, c01 = acc[mi][ni][1] + bb1;
            float c10 = acc[mi][ni][2] + bb0, c11 = acc[mi][ni][3] + bb1;
            int h = col >> 6, d = col & 63;
            int b0r = r0 >> 11, s0 = r0 & 2047;
            int b1r = r1 >> 11, s1 = r1 & 2047;
            *(uint32_t*)&out[(((size_t)(b0r * H_ + h) * S_ + s0) << 6) + d] = ph2(c00, c01);
            *(uint32_t*)&out[(((size_t)(b1r * H_ + h) * S_ + s1) << 6) + d] = ph2(c10, c11);
        }
    }
}

// ---------------------------------------------------------------------------
// gemm_out: 128x64 N-tiles (768 blocks, kills wave tail), BK=64, fp16 mma.
// Smem: Xs[2][128][36] + Ws[2][64][36] = 55296 B.
// ---------------------------------------------------------------------------
#define WP2 36
#define WBUFW2 (64 * WP2)
#define GEMM2_SMEM ((2 * XBUFW + 2 * WBUFW2) * 4)

__global__ __launch_bounds__(256, 3) void gemm_out(
    const __half* __restrict__ X, const __half* __restrict__ W,
    const float* __restrict__ bias, float* __restrict__ out)
{
    extern __shared__ uint32_t sh[];
    const int m0 = blockIdx.y * 128, n0 = blockIdx.x * 64;

    uint32_t sbase;
    asm("{ .reg .u64 t0; cvta.to.shared.u64 t0, %1; cvt.u32.u64 %0, t0; }"
        : "=r"(sbase) : "l"(sh));

    const int tid  = threadIdx.x;
    const int w    = tid >> 5;
    const int lane = tid & 31;
    const int g    = lane >> 2;
    const int t    = lane & 3;
    const int wm   = (w & 1) * 64;
    const int wn   = (w >> 1) * 16;

    float acc[4][2][4];
#pragma unroll
    for (int mi = 0; mi < 4; mi++)
#pragma unroll
        for (int ni = 0; ni < 2; ni++)
#pragma unroll
            for (int r = 0; r < 4; r++) acc[mi][ni][r] = 0.f;

    const uint32_t xbase = sbase +
        (uint32_t)((wm + (lane & 15)) * XP + (lane >> 4) * 4) * 4;
    const uint32_t wbase = sbase +
        (uint32_t)(GW_OFF + (lane & 15) * WP2 + wn / 2 + (lane >> 4) * 4) * 4;

    auto stage = [&](int k0, int buf) {
#pragma unroll
        for (int i = 0; i < 4; i++) {
            int u = tid + 256 * i;
            int r = u >> 3, c = u & 7;
            cpa16(sbase + (uint32_t)(buf * XBUFW + r * XP + c * 4) * 4,
                  X + (size_t)(m0 + r) * HID_ + k0 + c * 8);
        }
#pragma unroll
        for (int i = 0; i < 2; i++) {
            int u = tid + 256 * i;
            int r = u >> 3, c = u & 7;
            cpa16(sbase + (uint32_t)(GW_OFF + buf * WBUFW2 + r * WP2 + c * 4) * 4,
                  W + (size_t)(k0 + r) * HID_ + n0 + c * 8);
        }
    };

    stage(0, 0);
    CP_COMMIT(); CP_WAIT0();
    __syncthreads();

    int buf = 0;
    for (int kt = 0; kt < 12; kt++) {
        if (kt < 11) { stage((kt + 1) * 64, buf ^ 1); CP_COMMIT(); }

#pragma unroll
        for (int s = 0; s < 4; s++) {
            uint32_t a[4][4];
#pragma unroll
            for (int mi = 0; mi < 4; mi++)
                ldsm4(a[mi][0], a[mi][1], a[mi][2], a[mi][3],
                      xbase + (uint32_t)(buf * XBUFW + mi * 16 * XP + s * 8) * 4);
            uint32_t b0, b1, b2, b3;
            ldsm4t(b0, b1, b2, b3,
                   wbase + (uint32_t)(buf * WBUFW2 + s * 16 * WP2) * 4);
#pragma unroll
            for (int mi = 0; mi < 4; mi++) {
                mma16(acc[mi][0], a[mi][0], a[mi][1], a[mi][2], a[mi][3], b0, b1);
                mma16(acc[mi][1], a[mi][0], a[mi][1], a[mi][2], a[mi][3], b2, b3);
            }
        }

        if (kt < 11) CP_WAIT0();
        __syncthreads();
        buf ^= 1;
    }

#pragma unroll
    for (int mi = 0; mi < 4; mi++) {
        int r0 = m0 + wm + 16 * mi + g;
        int r1 = r0 + 8;
#pragma unroll
        for (int ni = 0; ni < 2; ni++) {
            int col = n0 + wn + 8 * ni + 2 * t;
            float bb0 = bias[col], bb1 = bias[col + 1];
            *(float2*)&out[(size_t)r0 * HID_ + col] =
                make_float2(acc[mi][ni][0] + bb0, acc[mi][ni][1] + bb1);
            *(float2*)&out[(size_t)r1 * HID_ + col] =
                make_float2(acc[mi][ni][2] + bb0, acc[mi][ni][3] + bb1);
        }
    }
}

// ---------------------------------------------------------------------------
// attn_pass1: QK mma -> masked e = exp2(s*C2) -> e store (fragment-native)
// + row sums -> g_rsum.  Smem: Qs[128][36] + Kb[2][64][36] = 36864 B.
// ---------------------------------------------------------------------------
#define FP_ 36
#define KBUFW (64 * FP_)
#define Q_OFF 0
#define K_OFF (128 * FP_)
#define P1_SMEM ((K_OFF + 2 * KBUFW) * 4)

__global__ __launch_bounds__(256, 2) void attn_pass1(
    const __half* __restrict__ qg, const __half* __restrict__ kg,
    const uint32_t* __restrict__ bm, uint32_t* __restrict__ escr,
    float* __restrict__ rsum)
{
    extern __shared__ uint32_t sh[];
    uint32_t sbase;
    asm("{ .reg .u64 t0; cvta.to.shared.u64 t0, %1; cvt.u32.u64 %0, t0; }"
        : "=r"(sbase) : "l"(sh));

    const int tid  = threadIdx.x;
    const int w    = tid >> 5;
    const int lane = tid & 31;
    const int g    = lane >> 2;
    const int t    = lane & 3;
    const int wr   = w * 16;
    const int q0   = blockIdx.x * 128;
    const int bh   = blockIdx.y;
    const int bb   = bh / H_;
    const __half* qbase = qg + (size_t)bh * S_ * D_;
    const __half* kbase = kg + (size_t)bh * S_ * D_;

    const int lr0 = wr + g;
    const int lr1 = lr0 + 8;
    const int r0  = q0 + lr0;
    const int r1  = q0 + lr1;
    const uint32_t* bm0 = bm + ((size_t)bb * S_ + r0) * 64;
    const uint32_t* bm1 = bm + ((size_t)bb * S_ + r1) * 64;

    uint32_t* eb = escr + (((size_t)bh * 16 + blockIdx.x) * 32) * 4096 + tid * 4;

    const int arow = wr + (lane & 15);
    const int ahi  = (lane >> 4) * 4;
    const int brow = (lane & 7) + ((lane >> 1) & 8);
    const int bhi  = ((lane >> 3) & 1) * 4;
    const uint32_t qaddr  = sbase + (uint32_t)(Q_OFF + arow * FP_ + ahi) * 4;
    const uint32_t kaddr0 = sbase + (uint32_t)(K_OFF + brow * FP_ + bhi) * 4;

    const int cr0 = tid >> 2, cc0 = (tid & 3) * 2;

#pragma unroll
    for (int i = 0; i < 4; i++) {
        int u = tid + 256 * i;
        int r = u >> 3, c = u & 7;
        cpa16(sbase + (uint32_t)(Q_OFF + r * FP_ + c * 4) * 4,
              qbase + (size_t)(q0 + r) * D_ + c * 8);
    }
#pragma unroll
    for (int i = 0; i < 2; i++)
        cpa16(sbase + (uint32_t)(K_OFF + cr0 * FP_ + (cc0 + i) * 4) * 4,
              kbase + (size_t)cr0 * D_ + (cc0 + i) * 8);
    CP_COMMIT();
    CP_WAIT0();
    __syncthreads();

    uint32_t qa[4][4];
#pragma unroll
    for (int s = 0; s < 4; s++)
        ldsm4(qa[s][0], qa[s][1], qa[s][2], qa[s][3], qaddr + s * 32);

    float s0v = 0.f, s1v = 0.f;
    int buf = 0;

    for (int kt = 0; kt < 32; kt++) {
        if (kt < 31) {
            const __half* src = kbase + (size_t)(kt + 1) * 64 * D_;
            uint32_t dst = sbase + (uint32_t)(K_OFF + (buf ^ 1) * KBUFW) * 4;
#pragma unroll
            for (int i = 0; i < 2; i++)
                cpa16(dst + (uint32_t)(cr0 * FP_ + (cc0 + i) * 4) * 4,
                      src + (size_t)cr0 * D_ + (cc0 + i) * 8);
            CP_COMMIT();
        }

        float acc[8][4];
#pragma unroll
        for (int ni = 0; ni < 8; ni++)
#pragma unroll
            for (int r = 0; r < 4; r++) acc[ni][r] = 0.f;

        uint32_t ka = kaddr0 + (uint32_t)(buf * KBUFW) * 4;
#pragma unroll
        for (int s = 0; s < 4; s++) {
            uint32_t kb[16];
#pragma unroll
            for (int j = 0; j < 4; j++)
                ldsm4(kb[4 * j], kb[4 * j + 1], kb[4 * j + 2], kb[4 * j + 3],
                      ka + (uint32_t)(16 * j * FP_ + s * 8) * 4);
#pragma unroll
            for (int ni = 0; ni < 8; ni++)
                mma16(acc[ni], qa[s][0], qa[s][1], qa[s][2], qa[s][3],
                      kb[2 * ni], kb[2 * ni + 1]);
        }

        int k0 = kt * 64;
        uint2 w0 = *(const uint2*)(bm0 + (k0 >> 5));
        uint2 w1 = *(const uint2*)(bm1 + (k0 >> 5));
        uint32_t ue[16];
#pragma unroll
        for (int ni = 0; ni < 8; ni++) {
            uint32_t sel0 = (ni < 4) ? w0.x : w0.y;
            uint32_t sel1 = (ni < 4) ? w1.x : w1.y;
            int bit = (8 * ni + 2 * t) & 31;
            float e00 = ((sel0 >> bit) & 1)       ? 0.f : exp2f(acc[ni][0] * C2_);
            float e01 = ((sel0 >> (bit + 1)) & 1) ? 0.f : exp2f(acc[ni][1] * C2_);
            float e10 = ((sel1 >> bit) & 1)       ? 0.f : exp2f(acc[ni][2] * C2_);
            float e11 = ((sel1 >> (bit + 1)) & 1) ? 0.f : exp2f(acc[ni][3] * C2_);
            s0v += e00 + e01;
            s1v += e10 + e11;
            ue[2 * ni]     = ph2(e00, e01);
            ue[2 * ni + 1] = ph2(e10, e11);
        }
        uint32_t* ep = eb + (size_t)kt * 4096;
#pragma unroll
        for (int i4 = 0; i4 < 4; i4++)
            *(uint4*)(ep + i4 * 1024) = *(const uint4*)&ue[4 * i4];

        if (kt < 31) CP_WAIT0();
        __syncthreads();
        buf ^= 1;
    }

    s0v += __shfl_xor_sync(0xffffffffu, s0v, 1);
    s0v += __shfl_xor_sync(0xffffffffu, s0v, 2);
    s1v += __shfl_xor_sync(0xffffffffu, s1v, 1);
    s1v += __shfl_xor_sync(0xffffffffu, s1v, 2);
    if (t == 0) {
        rsum[(size_t)bh * S_ + r0] = s0v;
        rsum[(size_t)bh * S_ + r1] = s1v;
    }
}

// ---------------------------------------------------------------------------
// attn_pass2: e reload -> probs write + PV (e regs ARE A-fragments).
// Smem: Vb[2][64][36] = 18432 B only -> 3 CTAs/SM.
// ---------------------------------------------------------------------------
#define P2_SMEM (2 * KBUFW * 4)

__global__ __launch_bounds__(256, 3) void attn_pass2(
    const __half* __restrict__ vg, const float* __restrict__ rsum,
    const uint32_t* __restrict__ escr,
    float* __restrict__ probs, __half* __restrict__ ctx)
{
    extern __shared__ uint32_t sh[];
    uint32_t sbase;
    asm("{ .reg .u64 t0; cvta.to.shared.u64 t0, %1; cvt.u32.u64 %0, t0; }"
        : "=r"(sbase) : "l"(sh));

    const int tid  = threadIdx.x;
    const int w    = tid >> 5;
    const int lane = tid & 31;
    const int g    = lane >> 2;
    const int t    = lane & 3;
    const int wr   = w * 16;
    const int q0   = blockIdx.x * 128;
    const int bh   = blockIdx.y;
    const int bb   = bh / H_;
    const int h    = bh % H_;
    const __half* vbase = vg + (size_t)bh * S_ * D_;

    const int lr0 = wr + g;
    const int lr1 = lr0 + 8;
    const int r0  = q0 + lr0;
    const int r1  = q0 + lr1;

    const float inv0 = 1.f / rsum[(size_t)bh * S_ + r0];
    const float inv1 = 1.f / rsum[(size_t)bh * S_ + r1];

    const uint32_t* eb = escr + (((size_t)bh * 16 + blockIdx.x) * 32) * 4096 + tid * 4;

    const int vrow = lane & 15;
    const int vhi  = (lane >> 4) * 4;
    const uint32_t vaddr0 = sbase + (uint32_t)(vrow * FP_ + vhi) * 4;

    const int cr0 = tid >> 2, cc0 = (tid & 3) * 2;

    float accv[8][4];
#pragma unroll
    for (int ni = 0; ni < 8; ni++)
#pragma unroll
        for (int r = 0; r < 4; r++) accv[ni][r] = 0.f;

    float* pr0 = probs + ((size_t)bh * S_ + r0) * S_;
    float* pr1 = probs + ((size_t)bh * S_ + r1) * S_;

    // Preload V tile 0 + e tile 0
    int buf = 0;
#pragma unroll
    for (int i = 0; i < 2; i++)
        cpa16(sbase + (uint32_t)(cr0 * FP_ + (cc0 + i) * 4) * 4,
              vbase + (size_t)cr0 * D_ + (cc0 + i) * 8);
    CP_COMMIT();

    uint32_t uc[16];
#pragma unroll
    for (int i4 = 0; i4 < 4; i4++)
        *(uint4*)&uc[4 * i4] = *(const uint4*)(eb + i4 * 1024);

    CP_WAIT0();
    __syncthreads();

    for (int kt = 0; kt < 32; kt++) {
        uint32_t un[16];
        if (kt < 31) {
            const uint32_t* ep = eb + (size_t)(kt + 1) * 4096;
#pragma unroll
            for (int i4 = 0; i4 < 4; i4++)
                *(uint4*)&un[4 * i4] = *(const uint4*)(ep + i4 * 1024);
            const __half* vsrc = vbase + (size_t)(kt + 1) * 64 * D_;
            uint32_t vdst = sbase + (uint32_t)((buf ^ 1) * KBUFW) * 4;
#pragma unroll
            for (int i = 0; i < 2; i++)
                cpa16(vdst + (uint32_t)(cr0 * FP_ + (cc0 + i) * 4) * 4,
                      vsrc + (size_t)cr0 * D_ + (cc0 + i) * 8);
            CP_COMMIT();
        }

        int k0 = kt * 64;
#pragma unroll
        for (int ni = 0; ni < 8; ni++) {
            float2 e0 = __half22float2(*(const __half2*)&uc[2 * ni]);
            float2 e1 = __half22float2(*(const __half2*)&uc[2 * ni + 1]);
            int c = k0 + 8 * ni + 2 * t;
            __stcs((float2*)(pr0 + c), make_float2(e0.x * inv0, e0.y * inv0));
            __stcs((float2*)(pr1 + c), make_float2(e1.x * inv1, e1.y * inv1));
        }

        uint32_t va = vaddr0 + (uint32_t)(buf * KBUFW) * 4;
#pragma unroll
        for (int s = 0; s < 4; s++) {
#pragma unroll
            for (int j = 0; j < 4; j++) {
                uint32_t vb0, vb1, vb2, vb3;
                ldsm4t(vb0, vb1, vb2, vb3,
                       va + (uint32_t)(16 * s * FP_ + 8 * j) * 4);
                mma16(accv[2 * j],     uc[4 * s], uc[4 * s + 1], uc[4 * s + 2], uc[4 * s + 3], vb0, vb1);
                mma16(accv[2 * j + 1], uc[4 * s], uc[4 * s + 1], uc[4 * s + 2], uc[4 * s + 3], vb2, vb3);
            }
        }

        if (kt < 31) {
            CP_WAIT0();
#pragma unroll
            for (int i = 0; i < 16; i++) uc[i] = un[i];
        }
        __syncthreads();
        buf ^= 1;
    }

#pragma unroll
    for (int ni = 0; ni < 8; ni++) {
        int col = h * D_ + 8 * ni + 2 * t;
        *(uint32_t*)&ctx[((size_t)(bb * S_ + r0)) * HID_ + col] =
            ph2(accv[ni][0] * inv0, accv[ni][1] * inv0);
        *(uint32_t*)&ctx[((size_t)(bb * S_ + r1)) * HID_ + col] =
            ph2(accv[ni][2] * inv1, accv[ni][3] * inv1);
    }
}

// ---------------------------------------------------------------------------
extern "C" void kernel_launch(void* const* d_in, const int* in_sizes, int n_in,
                              void* d_out, int out_size)
{
    (void)in_sizes; (void)n_in; (void)out_size;
    const float* Q  = (const float*)d_in[0];
    const float* K  = (const float*)d_in[1];
    const float* V  = (const float*)d_in[2];
    const int*   mask = (const int*)d_in[3];
    const float* Wq = (const float*)d_in[4];
    const float* bq = (const float*)d_in[5];
    const float* Wk = (const float*)d_in[6];
    const float* bk = (const float*)d_in[7];
    const float* Wv = (const float*)d_in[8];
    const float* bv = (const float*)d_in[9];
    const float* Wo = (const float*)d_in[10];
    const float* bo = (const float*)d_in[11];

    float* out   = (float*)d_out;
    float* probs = out + OUTE;

    float* scratch = nullptr;
    cudaGetSymbolAddress((void**)&scratch, g_scratch);
    uint32_t* bmp = nullptr;
    cudaGetSymbolAddress((void**)&bmp, g_bm);
    uint32_t* escr = nullptr;
    cudaGetSymbolAddress((void**)&escr, g_escr);
    float* rsum = nullptr;
    cudaGetSymbolAddress((void**)&rsum, g_rsum);

    __half* rXq = (__half*)scratch;
    __half* rXk = rXq + (size_t)OUTE;
    __half* rXv = rXk + (size_t)OUTE;
    __half* rWq = rXv + (size_t)OUTE;
    __half* rWk = rWq + WE;
    __half* rWv = rWk + WE;
    __half* rWo = rWv + WE;
    __half* gq  = rWo + WE;
    __half* gk  = gq + (size_t)OUTE;
    __half* gv  = gk + (size_t)OUTE;
    __half* gctx = gv + (size_t)OUTE;

    cudaFuncSetAttribute(attn_pass1, cudaFuncAttributeMaxDynamicSharedMemorySize,
                         P1_SMEM);
    cudaFuncSetAttribute(attn_pass2, cudaFuncAttributeMaxDynamicSharedMemorySize,
                         P2_SMEM);
    cudaFuncSetAttribute(gemm_qkv, cudaFuncAttributeMaxDynamicSharedMemorySize,
                         GEMM_SMEM);
    cudaFuncSetAttribute(gemm_out, cudaFuncAttributeMaxDynamicSharedMemorySize,
                         GEMM2_SMEM);

    prep_all<<<22784, 256>>>(Q, K, V, Wq, Wk, Wv, Wo,
                             rXq, rXk, rXv, rWq, rWk, rWv, rWo, mask, bmp);

    gemm_qkv<<<dim3(HID_ / 128, MROWS / 128, 3), 256, GEMM_SMEM>>>(
        rXq, rXk, rXv, rWq, rWk, rWv, bq, bk, bv, gq, gk, gv);
    attn_pass1<<<dim3(S_ / 128, BH_), 256, P1_SMEM>>>(gq, gk, bmp, escr, rsum);
    attn_pass2<<<dim3(S_ / 128, BH_), 256, P2_SMEM>>>(gv, rsum, escr, probs, gctx);
    gemm_out<<<dim3(HID_ / 64, MROWS / 128), 256, GEMM2_SMEM>>>(gctx, rWo, bo, out);
}